// round 9
// baseline (speedup 1.0000x reference)
#include <cuda_runtime.h>
#include <cuda_bf16.h>
#include <math.h>

// Problem dims
#define Hn 512
#define Dn 128
#define Nn 64
#define Tn 512

// K3 topology: 16 clusters (sequence groups) x 8 CTAs (j-slices)
#define K3_CL  8          // cluster size = j-slices
#define K3_NP  4          // sequences per CTA/cluster-group
#define K3_JC  64         // hidden-state columns per CTA
#define PP_S   516        // P_s row stride (floats)
#define AW_S   520        // a_s row stride (floats)

// ---------------- device scratch (static globals: no allocation) -------------
__device__ float g_E[(size_t)Tn * Nn * Hn];   // emit, then exp(emit - m); [t][n][h]
__device__ float g_M[Tn * Nn];                // rowmax m[t][n]
__device__ float g_Wt[Dn * Hn];               // W^T: [d][h]
__device__ float g_bias[Hn];

// ---------------- helpers -----------------------------------------------------
__device__ __forceinline__ unsigned long long ffma2(unsigned long long a,
                                                    unsigned long long b,
                                                    unsigned long long c) {
    unsigned long long d;
    asm("fma.rn.f32x2 %0, %1, %2, %3;" : "=l"(d) : "l"(a), "l"(b), "l"(c));
    return d;
}
__device__ __forceinline__ float2 up2(unsigned long long v) {
    float2 r;
    asm("mov.b64 {%0, %1}, %2;" : "=f"(r.x), "=f"(r.y) : "l"(v));
    return r;
}
__device__ __forceinline__ unsigned smem_u32(const void* p) {
    return (unsigned)__cvta_generic_to_shared(p);
}
__device__ __forceinline__ unsigned mapa_rank(unsigned saddr, unsigned rank) {
    unsigned r;
    asm("mapa.shared::cluster.u32 %0, %1, %2;" : "=r"(r) : "r"(saddr), "r"(rank));
    return r;
}
__device__ __forceinline__ void st_cluster_f32(unsigned addr, float v) {
    asm volatile("st.shared::cluster.f32 [%0], %1;" :: "r"(addr), "f"(v));
}
__device__ __forceinline__ void cluster_sync_hw() {
    asm volatile("barrier.cluster.arrive.aligned;" ::: "memory");
    asm volatile("barrier.cluster.wait.aligned;" ::: "memory");
}

// ---------------- K0: W^T and bias ------------------------------------------
__global__ void hmm_k0(const float* __restrict__ py) {
    int h = blockIdx.x * 8 + (threadIdx.x >> 5);
    int lane = threadIdx.x & 31;
    float s = 0.f;
#pragma unroll
    for (int c = 0; c < 4; c++) {
        int d = lane + c * 32;
        float p = __ldg(py + (size_t)h * Dn + d);
        float l1 = log1pf(-p);
        g_Wt[(size_t)d * Hn + h] = logf(p) - l1;
        s += l1;
    }
#pragma unroll
    for (int o = 16; o; o >>= 1) s += __shfl_xor_sync(0xffffffffu, s, o);
    if (lane == 0) g_bias[h] = s;
}

// ---------------- K1: emission GEMM  emit[t][n][h] = seq[n,t,:]*W^T + b ------
#define K1_SMEM ((64 * 132 + 128 * 128) * 4)
__global__ void __launch_bounds__(256) hmm_k1(const float* __restrict__ seq) {
    extern __shared__ float sm1[];
    float* seq_s = sm1;              // [64][132]
    float* W_s   = sm1 + 64 * 132;   // [128 k][128 h]

    int tid = threadIdx.x;
    int tb = blockIdx.y;
    int h0 = blockIdx.x * 128;

    for (int idx = tid; idx < 64 * 32; idx += 256) {
        int n = idx >> 5, d4 = idx & 31;
        float4 v = __ldg((const float4*)(seq + ((size_t)n * Tn + tb) * Dn + d4 * 4));
        *(float4*)&seq_s[n * 132 + d4 * 4] = v;
    }
    for (int idx = tid; idx < 128 * 32; idx += 256) {
        int k = idx >> 5, h4 = idx & 31;
        float4 v = __ldg((const float4*)(g_Wt + (size_t)k * Hn + h0 + h4 * 4));
        *(float4*)&W_s[k * 128 + h4 * 4] = v;
    }
    __syncthreads();

    int tx = tid & 15;
    int ty = tid >> 4;
    float acc[4][8];
#pragma unroll
    for (int u = 0; u < 4; u++)
#pragma unroll
        for (int v = 0; v < 8; v++) acc[u][v] = 0.f;

#pragma unroll 4
    for (int k = 0; k < 128; k++) {
        float aa[4];
#pragma unroll
        for (int u = 0; u < 4; u++) aa[u] = seq_s[(ty * 4 + u) * 132 + k];
        float4 b0 = *(const float4*)&W_s[k * 128 + tx * 8];
        float4 b1 = *(const float4*)&W_s[k * 128 + tx * 8 + 4];
        float bb[8] = {b0.x, b0.y, b0.z, b0.w, b1.x, b1.y, b1.z, b1.w};
#pragma unroll
        for (int u = 0; u < 4; u++)
#pragma unroll
            for (int v = 0; v < 8; v++) acc[u][v] = fmaf(aa[u], bb[v], acc[u][v]);
    }

    float4 bi0 = *(const float4*)&g_bias[h0 + tx * 8];
    float4 bi1 = *(const float4*)&g_bias[h0 + tx * 8 + 4];
    float bb[8] = {bi0.x, bi0.y, bi0.z, bi0.w, bi1.x, bi1.y, bi1.z, bi1.w};
#pragma unroll
    for (int u = 0; u < 4; u++) {
        size_t r = (size_t)tb * 64 + ty * 4 + u;
        float4 o0 = make_float4(acc[u][0] + bb[0], acc[u][1] + bb[1],
                                acc[u][2] + bb[2], acc[u][3] + bb[3]);
        float4 o1 = make_float4(acc[u][4] + bb[4], acc[u][5] + bb[5],
                                acc[u][6] + bb[6], acc[u][7] + bb[7]);
        *(float4*)&g_E[r * Hn + h0 + tx * 8]     = o0;
        *(float4*)&g_E[r * Hn + h0 + tx * 8 + 4] = o1;
    }
}

// ---------------- K2: rowmax + exp(emit - m), in place; write m --------------
__global__ void __launch_bounds__(256) hmm_k2() {
    int r = blockIdx.x * 8 + (threadIdx.x >> 5);
    int lane = threadIdx.x & 31;
    float* row = g_E + (size_t)r * Hn;
    float4 v[4];
    float m = -3.0e38f;
#pragma unroll
    for (int c = 0; c < 4; c++) {
        v[c] = *(const float4*)(row + c * 128 + lane * 4);
        m = fmaxf(m, fmaxf(fmaxf(v[c].x, v[c].y), fmaxf(v[c].z, v[c].w)));
    }
#pragma unroll
    for (int o = 16; o; o >>= 1) m = fmaxf(m, __shfl_xor_sync(0xffffffffu, m, o));
#pragma unroll
    for (int c = 0; c < 4; c++) {
        float4 e = make_float4(__expf(v[c].x - m), __expf(v[c].y - m),
                               __expf(v[c].z - m), __expf(v[c].w - m));
        *(float4*)(row + c * 128 + lane * 4) = e;
    }
    if (lane == 0) g_M[r] = m;
}

// ---------------- K3: cluster-based scaled-forward recursion -----------------
// smem: P_s[64][516] | a_s[2][4][520] | ps_s[2][8][4] | wp_s[32] | len_s[4]
#define K3_SMEM ((K3_JC * PP_S + 2 * K3_NP * AW_S + 64 + 32 + 4) * 4)
__global__ void __launch_bounds__(256, 1) __cluster_dims__(K3_CL, 1, 1)
hmm_k3(const float* __restrict__ px, const int* __restrict__ lengths,
       float* __restrict__ out) {
    extern __shared__ float sm3[];
    float* P_s   = sm3;                               // [64][516]
    float* a_s   = sm3 + K3_JC * PP_S;                // [2][4][520]
    float* ps_s  = a_s + 2 * K3_NP * AW_S;            // [2][8][4]
    float* wp_s  = ps_s + 64;                         // [8 warps][4 seq]
    int*   len_s = (int*)(wp_s + 32);                 // [4]

    const int tid  = threadIdx.x;
    const int w    = tid >> 5;
    const int lane = tid & 31;
    unsigned rank;
    asm("mov.u32 %0, %%cluster_ctarank;" : "=r"(rank));
    const int g  = blockIdx.x >> 3;                   // sequence group 0..15
    const int n0 = g * K3_NP;
    const int j0 = (int)rank * K3_JC;

    // P slice -> smem: P_s[jc][i] = px[i*512 + j0+jc]
    for (int idx = tid; idx < 512 * K3_JC; idx += 256) {
        int jc = idx & 63, i = idx >> 6;
        P_s[jc * PP_S + i] = __ldg(px + (size_t)i * Hn + j0 + jc);
    }
    if (tid < K3_NP) len_s[tid] = __ldg(lengths + n0 + tid);
    __syncthreads();

    const int nloc  = lane >> 3;                      // 0..3 sequence
    const int jq    = lane & 7;
    const int jrow  = (w << 3) | jq;                  // 0..63 local column
    const int jglob = j0 + jrow;
    const int lenreg = len_s[nloc];
    const size_t ecol = (size_t)(n0 + nloc) * Hn + jglob;

    // remote-store addresses (same local offset in every rank's smem)
    const unsigned a_addr0 = smem_u32(&a_s[(0 * K3_NP + nloc) * AW_S + jglob]);
    const unsigned a_addr1 = smem_u32(&a_s[(1 * K3_NP + nloc) * AW_S + jglob]);
    unsigned ps_addr0 = 0, ps_addr1 = 0, ps_rank = 0;
    if (w == 0) {
        ps_addr0 = smem_u32(&ps_s[(0 * 8 + rank) * 4 + (lane & 3)]);
        ps_addr1 = smem_u32(&ps_s[(1 * 8 + rank) * 4 + (lane & 3)]);
        ps_rank  = (unsigned)(lane >> 2);
    }

    // ---- t = 0 init: a0 = probs_x[0][j] * E[0][n][j];  Creg = m0 ----
    float accv = __ldg(px + jglob) * __ldcg(g_E + ecol);
#pragma unroll
    for (unsigned r = 0; r < K3_CL; r++)
        st_cluster_f32(mapa_rank(a_addr0, r), accv);
    {
        float s = accv;
        s += __shfl_xor_sync(0xffffffffu, s, 1);
        s += __shfl_xor_sync(0xffffffffu, s, 2);
        s += __shfl_xor_sync(0xffffffffu, s, 4);
        if (jq == 0) wp_s[w * 4 + nloc] = s;
    }
    float Creg = 0.f;
    const bool book = (rank == 0 && w == 0 && lane < 4);   // lane == sequence
    if (book) Creg = __ldg(g_M + n0 + lane);
    __syncthreads();
    if (w == 0) {
        float v = wp_s[lane];
        v += __shfl_xor_sync(0xffffffffu, v, 4);
        v += __shfl_xor_sync(0xffffffffu, v, 8);
        v += __shfl_xor_sync(0xffffffffu, v, 16);
        st_cluster_f32(mapa_rank(ps_addr0, ps_rank), v);
    }
    cluster_sync_hw();

    for (int t = 1; t < Tn; t++) {
        const int rb = (t - 1) & 1;
        const int wb = t & 1;

        // prefetches (independent of cluster-exchanged data)
        float e = __ldcg(g_E + (size_t)t * (Nn * Hn) + ecol);
        float mreg = 0.f;
        if (book) mreg = __ldg(g_M + (size_t)t * Nn + n0 + lane);

        // S_{t-1} from rank partials (smem, broadcast)
        float S = 0.f;
        const float* pb = ps_s + rb * 32;
#pragma unroll
        for (int r = 0; r < 8; r++) S += pb[r * 4 + nloc];
        float Rinv = __fdividef(1.0f, S);
        if (book && t < len_s[lane]) Creg += logf(S) + mreg;

        // 512-length dot: a_s[rb][nloc] . P_s[jrow]  (packed f32x2)
        const float* ap = a_s + (rb * K3_NP + nloc) * AW_S;
        const float* pp = P_s + jrow * PP_S;
        unsigned long long q0 = 0ull, q1 = 0ull, q2 = 0ull, q3 = 0ull;
#pragma unroll 8
        for (int i = 0; i < 512; i += 8) {
            ulonglong2 a0 = *(const ulonglong2*)(ap + i);
            ulonglong2 p0 = *(const ulonglong2*)(pp + i);
            ulonglong2 a1 = *(const ulonglong2*)(ap + i + 4);
            ulonglong2 p1 = *(const ulonglong2*)(pp + i + 4);
            q0 = ffma2(a0.x, p0.x, q0); q1 = ffma2(a0.y, p0.y, q1);
            q2 = ffma2(a1.x, p1.x, q2); q3 = ffma2(a1.y, p1.y, q3);
        }
        float2 f0 = up2(q0), f1 = up2(q1), f2 = up2(q2), f3 = up2(q3);
        float tmp = ((f0.x + f0.y) + (f1.x + f1.y)) + ((f2.x + f2.y) + (f3.x + f3.y));

        float newv = tmp * Rinv * e;
        if (t < lenreg) accv = newv;               // frozen sequences copy-through

        // broadcast new alpha to all ranks' a_s[wb]
        const unsigned aw = wb ? a_addr1 : a_addr0;
#pragma unroll
        for (unsigned r = 0; r < K3_CL; r++)
            st_cluster_f32(mapa_rank(aw, r), accv);

        // local partial sums -> wp_s, then warp 0 reduces + broadcasts psums
        float s2 = accv;
        s2 += __shfl_xor_sync(0xffffffffu, s2, 1);
        s2 += __shfl_xor_sync(0xffffffffu, s2, 2);
        s2 += __shfl_xor_sync(0xffffffffu, s2, 4);
        if (jq == 0) wp_s[w * 4 + nloc] = s2;
        __syncthreads();
        if (w == 0) {
            float v = wp_s[lane];
            v += __shfl_xor_sync(0xffffffffu, v, 4);
            v += __shfl_xor_sync(0xffffffffu, v, 8);
            v += __shfl_xor_sync(0xffffffffu, v, 16);
            st_cluster_f32(mapa_rank(wb ? ps_addr1 : ps_addr0, ps_rank), v);
        }
        cluster_sync_hw();
    }

    // ---- output: rank-0 CTA, warp 0, lanes 0..3 own the 4 sequences ----
    if (book) {
        float Sf = 0.f;
        const float* pb = ps_s + ((Tn - 1) & 1) * 32;
#pragma unroll
        for (int r = 0; r < 8; r++) Sf += pb[r * 4 + lane];
        out[n0 + lane] = Creg + logf(Sf);
    }
}

// ---------------- launch ------------------------------------------------------
extern "C" void kernel_launch(void* const* d_in, const int* in_sizes, int n_in,
                              void* d_out, int out_size) {
    const float* seq = nullptr;
    const int*   len = nullptr;
    const float* px  = nullptr;
    const float* py  = nullptr;
    for (int i = 0; i < n_in; i++) {
        switch (in_sizes[i]) {
            case Nn * Tn * Dn: seq = (const float*)d_in[i]; break;
            case Nn:           len = (const int*)d_in[i];   break;
            case Hn * Hn:      px  = (const float*)d_in[i]; break;
            case Hn * Dn:      py  = (const float*)d_in[i]; break;
        }
    }

    cudaFuncSetAttribute(hmm_k1, cudaFuncAttributeMaxDynamicSharedMemorySize, K1_SMEM);
    cudaFuncSetAttribute(hmm_k3, cudaFuncAttributeMaxDynamicSharedMemorySize, K3_SMEM);

    hmm_k0<<<64, 256>>>(py);
    hmm_k1<<<dim3(4, 512), 256, K1_SMEM>>>(seq);
    hmm_k2<<<4096, 256>>>();
    hmm_k3<<<16 * K3_CL, 256, K3_SMEM>>>(px, len, (float*)d_out);
}

// round 10
// speedup vs baseline: 1.9521x; 1.9521x over previous
#include <cuda_runtime.h>
#include <cuda_bf16.h>
#include <math.h>

// Problem dims
#define Hn 512
#define Dn 128
#define Nn 64
#define Tn 512

// K3 layout: 128 persistent CTAs = 8 n-groups x 16 j-slices
#define K3_G  8
#define K3_J  16
#define K3_NP 8          // sequences per group (1 per warp)
#define K3_JC 32         // hidden-state columns per CTA (1 per lane)
#define AP    516        // padded a_s row stride

// ---------------- device scratch (static globals: no allocation) -------------
__device__ float g_E[(size_t)Tn * Nn * Hn];   // emit, then exp(emit - m); [t][n][h]
__device__ float g_M[Tn * Nn];                // rowmax m[t][n]
__device__ float g_Wt[Dn * Hn];               // W^T: [d][h]
__device__ float g_bias[Hn];
__device__ float g_alpha[2][(size_t)Nn * Hn]; // double-buffered scaled alpha
__device__ unsigned g_cnt2[K3_G * 32];        // per-group barrier counters (padded)
__device__ volatile unsigned g_gen2[K3_G * 32];

// ---------------- packed f32x2 helpers ---------------------------------------
__device__ __forceinline__ unsigned long long ffma2(unsigned long long a,
                                                    unsigned long long b,
                                                    unsigned long long c) {
    unsigned long long d;
    asm("fma.rn.f32x2 %0, %1, %2, %3;" : "=l"(d) : "l"(a), "l"(b), "l"(c));
    return d;
}
__device__ __forceinline__ float2 up2(unsigned long long v) {
    float2 r;
    asm("mov.b64 {%0, %1}, %2;" : "=f"(r.x), "=f"(r.y) : "l"(v));
    return r;
}
__device__ __forceinline__ unsigned long long pack2(float lo, float hi) {
    unsigned long long v;
    asm("mov.b64 %0, {%1, %2};" : "=l"(v) : "f"(lo), "f"(hi));
    return v;
}

// ---------------- K0: W^T and bias ------------------------------------------
__global__ void hmm_k0(const float* __restrict__ py) {
    int h = blockIdx.x * 8 + (threadIdx.x >> 5);
    int lane = threadIdx.x & 31;
    float s = 0.f;
#pragma unroll
    for (int c = 0; c < 4; c++) {
        int d = lane + c * 32;
        float p = __ldg(py + (size_t)h * Dn + d);
        float l1 = log1pf(-p);
        g_Wt[(size_t)d * Hn + h] = logf(p) - l1;
        s += l1;
    }
#pragma unroll
    for (int o = 16; o; o >>= 1) s += __shfl_xor_sync(0xffffffffu, s, o);
    if (lane == 0) g_bias[h] = s;
}

// ---------------- K1: emission GEMM  emit[t][n][h] = seq[n,t,:]*W^T + b ------
#define K1_SMEM ((64 * 132 + 128 * 128) * 4)
__global__ void __launch_bounds__(256) hmm_k1(const float* __restrict__ seq) {
    extern __shared__ float sm1[];
    float* seq_s = sm1;              // [64][132]
    float* W_s   = sm1 + 64 * 132;   // [128 k][128 h]

    int tid = threadIdx.x;
    int tb = blockIdx.y;
    int h0 = blockIdx.x * 128;

    for (int idx = tid; idx < 64 * 32; idx += 256) {
        int n = idx >> 5, d4 = idx & 31;
        float4 v = __ldg((const float4*)(seq + ((size_t)n * Tn + tb) * Dn + d4 * 4));
        *(float4*)&seq_s[n * 132 + d4 * 4] = v;
    }
    for (int idx = tid; idx < 128 * 32; idx += 256) {
        int k = idx >> 5, h4 = idx & 31;
        float4 v = __ldg((const float4*)(g_Wt + (size_t)k * Hn + h0 + h4 * 4));
        *(float4*)&W_s[k * 128 + h4 * 4] = v;
    }
    __syncthreads();

    int tx = tid & 15;
    int ty = tid >> 4;
    float acc[4][8];
#pragma unroll
    for (int u = 0; u < 4; u++)
#pragma unroll
        for (int v = 0; v < 8; v++) acc[u][v] = 0.f;

#pragma unroll 4
    for (int k = 0; k < 128; k++) {
        float aa[4];
#pragma unroll
        for (int u = 0; u < 4; u++) aa[u] = seq_s[(ty * 4 + u) * 132 + k];
        float4 b0 = *(const float4*)&W_s[k * 128 + tx * 8];
        float4 b1 = *(const float4*)&W_s[k * 128 + tx * 8 + 4];
        float bb[8] = {b0.x, b0.y, b0.z, b0.w, b1.x, b1.y, b1.z, b1.w};
#pragma unroll
        for (int u = 0; u < 4; u++)
#pragma unroll
            for (int v = 0; v < 8; v++) acc[u][v] = fmaf(aa[u], bb[v], acc[u][v]);
    }

    float4 bi0 = *(const float4*)&g_bias[h0 + tx * 8];
    float4 bi1 = *(const float4*)&g_bias[h0 + tx * 8 + 4];
    float bb[8] = {bi0.x, bi0.y, bi0.z, bi0.w, bi1.x, bi1.y, bi1.z, bi1.w};
#pragma unroll
    for (int u = 0; u < 4; u++) {
        size_t r = (size_t)tb * 64 + ty * 4 + u;
        float4 o0 = make_float4(acc[u][0] + bb[0], acc[u][1] + bb[1],
                                acc[u][2] + bb[2], acc[u][3] + bb[3]);
        float4 o1 = make_float4(acc[u][4] + bb[4], acc[u][5] + bb[5],
                                acc[u][6] + bb[6], acc[u][7] + bb[7]);
        *(float4*)&g_E[r * Hn + h0 + tx * 8]     = o0;
        *(float4*)&g_E[r * Hn + h0 + tx * 8 + 4] = o1;
    }
}

// ---------------- K2: rowmax + exp(emit - m), in place; write m --------------
__global__ void __launch_bounds__(256) hmm_k2() {
    int r = blockIdx.x * 8 + (threadIdx.x >> 5);
    int lane = threadIdx.x & 31;
    float* row = g_E + (size_t)r * Hn;
    float4 v[4];
    float m = -3.0e38f;
#pragma unroll
    for (int c = 0; c < 4; c++) {
        v[c] = *(const float4*)(row + c * 128 + lane * 4);
        m = fmaxf(m, fmaxf(fmaxf(v[c].x, v[c].y), fmaxf(v[c].z, v[c].w)));
    }
#pragma unroll
    for (int o = 16; o; o >>= 1) m = fmaxf(m, __shfl_xor_sync(0xffffffffu, m, o));
#pragma unroll
    for (int c = 0; c < 4; c++) {
        float4 e = make_float4(__expf(v[c].x - m), __expf(v[c].y - m),
                               __expf(v[c].z - m), __expf(v[c].w - m));
        *(float4*)(row + c * 128 + lane * 4) = e;
    }
    if (lane == 0) g_M[r] = m;
}

// ---------------- per-group grid barrier (16 CTAs, self-resetting) -----------
__device__ __forceinline__ void gridbar(unsigned gb) {
    __threadfence();
    __syncthreads();
    if (threadIdx.x == 0) {
        unsigned gen = g_gen2[gb];
        unsigned a = atomicAdd(&g_cnt2[gb], 1u);
        if (a == K3_J - 1u) {
            atomicExch(&g_cnt2[gb], 0u);
            __threadfence();
            g_gen2[gb] = gen + 1u;
        } else {
            while (g_gen2[gb] == gen) { }
            __threadfence();
        }
    }
    __syncthreads();
}

// ---------------- K3: P-in-registers scaled-forward recursion ----------------
// Thread (w, lane): i-chunk = w*64 (P rows), j-column = j0 + lane.
// Dot reads of staged alpha are warp-uniform (broadcast LDS).
__global__ void __launch_bounds__(256, 1) hmm_k3(const float* __restrict__ px,
                                                 const int* __restrict__ lengths,
                                                 float* __restrict__ out) {
    __shared__ float a_s[K3_NP * AP];       // staged alpha rows [8][516]
    __shared__ float rsum[K3_NP * 8 * 32];  // partials [n][chunk][j]
    __shared__ float R_s[K3_NP];            // 1/S per sequence
    __shared__ int   len_s[K3_NP];

    const int tid  = threadIdx.x;
    const int w    = tid >> 5;              // warp = i-chunk / owner sequence
    const int lane = tid & 31;              // j-column within slice
    const int cta  = blockIdx.x;
    const int jsl  = cta & (K3_J - 1);
    const int g    = cta >> 4;
    const int n0   = g * K3_NP;
    const int j0   = jsl * K3_JC;
    const int jg   = j0 + lane;
    const unsigned gb = (unsigned)g * 32u;

    // P slice -> registers: Pp[k] packs P[w*64+2k][jg], P[w*64+2k+1][jg]
    unsigned long long Pp[32];
#pragma unroll
    for (int k = 0; k < 32; k++) {
        float p0 = __ldg(px + (size_t)(w * 64 + 2 * k)     * Hn + jg);
        float p1 = __ldg(px + (size_t)(w * 64 + 2 * k + 1) * Hn + jg);
        Pp[k] = pack2(p0, p1);
    }
    if (tid < K3_NP) len_s[tid] = __ldg(lengths + n0 + tid);
    __syncthreads();
    const int lenw = len_s[w];

    // ---- t = 0 init: a0 = probs_x[0][j] * E[0][n][j];  Creg = m0 ----
    float accv = __ldg(px + jg) * __ldcg(g_E + (size_t)(n0 + w) * Hn + jg);
    __stcg(&g_alpha[0][(size_t)(n0 + w) * Hn + jg], accv);
    float Creg = 0.f;
    if (jsl == 0 && lane == 0) Creg = __ldg(g_M + n0 + w);
    gridbar(gb);

    for (int t = 1; t < Tn; t++) {
        const int rb = (t - 1) & 1;
        const int wb = t & 1;

        // prefetches
        float e = __ldcg(g_E + ((size_t)t * Nn + n0 + w) * Hn + jg);
        float mreg = 0.f;
        if (jsl == 0 && lane == 0)
            mreg = __ldg(g_M + (size_t)t * Nn + n0 + w);

        // stage alpha row (warp w <-> sequence n0+w) + row sum S
        {
            const float* ar = g_alpha[rb] + (size_t)(n0 + w) * Hn;
            float ssum = 0.f;
#pragma unroll
            for (int c = 0; c < 4; c++) {
                int i = c * 128 + lane * 4;
                float4 v = __ldcg((const float4*)(ar + i));
                ssum += (v.x + v.y) + (v.z + v.w);
                *(float4*)&a_s[w * AP + i] = v;
            }
#pragma unroll
            for (int o = 16; o; o >>= 1) ssum += __shfl_xor_sync(0xffffffffu, ssum, o);
            if (lane == 0) {
                R_s[w] = 1.0f / ssum;
                if (jsl == 0 && t < lenw) Creg += logf(ssum) + mreg;
            }
        }
        __syncthreads();

        // partial dots: for each sequence n, over this thread's 64-i chunk
        float res[K3_NP];
#pragma unroll
        for (int n = 0; n < K3_NP; n++) {
            const ulonglong2* an = (const ulonglong2*)(a_s + n * AP + (w << 6));
            unsigned long long q0 = 0ull, q1 = 0ull;
#pragma unroll
            for (int k = 0; k < 16; k++) {
                ulonglong2 av = an[k];                 // broadcast LDS.128
                q0 = ffma2(av.x, Pp[2 * k],     q0);
                q1 = ffma2(av.y, Pp[2 * k + 1], q1);
            }
            float2 f0 = up2(q0), f1 = up2(q1);
            res[n] = (f0.x + f0.y) + (f1.x + f1.y);
        }
#pragma unroll
        for (int n = 0; n < K3_NP; n++)
            rsum[(n * 8 + w) * 32 + lane] = res[n];
        __syncthreads();

        // combine 8 i-chunks: warp w finishes sequence n0+w, column jg
        float tot = 0.f;
#pragma unroll
        for (int c = 0; c < 8; c++) tot += rsum[(w * 8 + c) * 32 + lane];
        float newv = tot * R_s[w] * e;
        if (t < lenw) accv = newv;                     // frozen copy-through
        __stcg(&g_alpha[wb][(size_t)(n0 + w) * Hn + jg], accv);
        gridbar(gb);
    }

    // ---- output: j-slice-0 CTAs, warp w <-> sequence n0+w ----
    if (jsl == 0) {
        const float* ar = g_alpha[(Tn - 1) & 1] + (size_t)(n0 + w) * Hn;
        float s = 0.f;
#pragma unroll
        for (int c = 0; c < 4; c++) {
            int i = c * 128 + lane * 4;
            float4 v = __ldcg((const float4*)(ar + i));
            s += (v.x + v.y) + (v.z + v.w);
        }
#pragma unroll
        for (int o = 16; o; o >>= 1) s += __shfl_xor_sync(0xffffffffu, s, o);
        if (lane == 0) out[n0 + w] = Creg + logf(s);
    }
}

// ---------------- launch ------------------------------------------------------
extern "C" void kernel_launch(void* const* d_in, const int* in_sizes, int n_in,
                              void* d_out, int out_size) {
    const float* seq = nullptr;
    const int*   len = nullptr;
    const float* px  = nullptr;
    const float* py  = nullptr;
    for (int i = 0; i < n_in; i++) {
        switch (in_sizes[i]) {
            case Nn * Tn * Dn: seq = (const float*)d_in[i]; break;
            case Nn:           len = (const int*)d_in[i];   break;
            case Hn * Hn:      px  = (const float*)d_in[i]; break;
            case Hn * Dn:      py  = (const float*)d_in[i]; break;
        }
    }

    cudaFuncSetAttribute(hmm_k1, cudaFuncAttributeMaxDynamicSharedMemorySize, K1_SMEM);

    hmm_k0<<<64, 256>>>(py);
    hmm_k1<<<dim3(4, 512), 256, K1_SMEM>>>(seq);
    hmm_k2<<<4096, 256>>>();
    hmm_k3<<<K3_G * K3_J, 256>>>(px, len, (float*)d_out);
}